// round 16
// baseline (speedup 1.0000x reference)
#include <cuda_runtime.h>
#include <cuda_fp16.h>
#include <cstdint>

#define IMG_W   1024
#define IMG_H   1024
#define IMG_PIX (IMG_W * IMG_H)
#define N_IMG   32
#define TOTAL_F ((size_t)N_IMG * IMG_PIX)
#define SMOOTH  1e-5
#define FULLM   0xffffffffu
#define NBANDS  11                    // bands 0..9: 93 rows; band 10: 94 rows
#define BROW0   93
#define STRIPS  10
#define ROWQ    (IMG_W / 4)           // quads (4 cols) per row

typedef __half2 h2;
struct HQ { h2 p, q; };               // 4 columns: p=(c0,c1), q=(c2,c3)

// Scratch (no cudaMalloc allowed): fp16 intermediates
__device__ __half g_bufA[2 * N_IMG * IMG_PIX];
__device__ __half g_bufB[2 * N_IMG * IMG_PIX];
__device__ __half g_skel[2 * N_IMG * IMG_PIX];
__device__ double g_sums[4];

__device__ __forceinline__ HQ mkHQ(h2 a, h2 b) { HQ r; r.p = a; r.q = b; return r; }
__device__ __forceinline__ h2 hc(unsigned short u) { return __half2half2(__ushort_as_half(u)); }
__device__ __forceinline__ HQ ldHQ(const uint2* p) {
    uint2 u = *p; HQ v;
    v.p = *(h2*)&u.x; v.q = *(h2*)&u.y; return v;
}
__device__ __forceinline__ void stHQ(uint2* p, HQ v) {
    uint2 u; u.x = *(unsigned*)&v.p; u.y = *(unsigned*)&v.q; *p = u;
}
__device__ __forceinline__ h2 shup(h2 v) {
    unsigned u = *(unsigned*)&v; u = __shfl_up_sync(FULLM, u, 1); return *(h2*)&u;
}
__device__ __forceinline__ h2 shdn(h2 v) {
    unsigned u = *(unsigned*)&v; u = __shfl_down_sync(FULLM, u, 1); return *(h2*)&u;
}

// One sweep step at row Y, ring slot U (compile-time). fp16 tower.
// Ring invariant after step Y: L[j][U] = level-j row (Y-j); (U+2)%3 = that row-1; (U+1)%3 = row-2.
// Input stream double-buffered (distance-2 prefetch): nx0 = row Y, nx1 = row Y+1;
// this step loads row Y+2 into nx1 after shifting. Skel stream likewise (sn0 = row Y-2).
template <int T, int U, bool INIT, bool WRITE_E, bool TOPB, bool BOTB, bool FUSE>
__device__ __forceinline__ void do_step(
    int Y, HQ (&L)[T + 1][3], HQ& nx0, HQ& nx1, HQ& sn0, HQ& sn1, float4& onxt,
    const float4*& inPf, const uint2*& inPh, uint2*& skP, const float4*& otP, uint2*& eoP,
    uint2* __restrict__ ring, float& acc_p, float& acc_s,
    int lane, bool loadok, bool outok, bool ledge, bool redge,
    int b0, int b1)
{
    const h2 INF2  = hc(0x7C00);
    const h2 NINF2 = hc(0xFC00);
    const h2 ZERO2 = hc(0x0000);
    const __half NINFh = __ushort_as_half(0xFC00);
    constexpr int u  = U;
    constexpr int h1 = (U + 2) % 3;
    constexpr int hh2 = (U + 1) % 3;

    // Advance stream pointers to row Y.
    if (INIT) inPf += ROWQ; else inPh += ROWQ;
    skP += ROWQ;
    if (FUSE) otP += ROWQ;
    if (WRITE_E) eoP += ROWQ;

    // Consume input row Y; shift; prefetch row Y+2 (distance 2).
    L[0][u] = nx0;
    nx0 = nx1;
    {
        const int yy = Y + 2;
        bool ok = loadok;
        if (TOPB) ok = ok && (yy >= 0);
        if (BOTB) ok = ok && (yy < IMG_H);
        HQ v = mkHQ(INF2, INF2);
        if (ok) {
            if (INIT) {
                float4 f = inPf[2 * ROWQ];
                v.p = __floats2half2_rn(f.x, f.y);
                v.q = __floats2half2_rn(f.z, f.w);
            } else {
                v = ldHQ(inPh + 2 * ROWQ);
            }
        }
        nx1 = v;
    }
    // Consume skel row Y-2; shift; prefetch row Y (distance 2).
    HQ scur = sn0;
    if (!INIT) {
        sn0 = sn1;
        const int yy = Y;
        HQ sv = mkHQ(ZERO2, ZERO2);
        if (yy >= b0 && yy < b1 && outok) sv = ldHQ(skP);
        sn1 = sv;
    }
    // Consume prefetched other row (Y-T-1, fp32); prefetch row Y-T (distance 1).
    float4 ocur = onxt;
    if (FUSE) {
        const int yy = Y - T;
        float4 ov = make_float4(0.0f, 0.0f, 0.0f, 0.0f);
        if (yy >= b0 && yy < b1 && outok) ov = otP[-T * ROWQ];
        onxt = ov;
    }

    // Erosion levels: level j computes row r = Y - j from level j-1 rows r-1..r+1
#pragma unroll
    for (int j = 1; j <= T; ++j) {
        const int r = Y - j;
        const HQ up = L[j - 1][hh2];
        const HQ ce = L[j - 1][h1];
        const HQ dn = L[j - 1][u];
        const h2 lf = shup(ce.q);   // left neighbor's (c2,c3)
        const h2 rt = shdn(ce.p);   // right neighbor's (c0,c1)
        const h2 mid = __halves2half2(__high2half(ce.p), __low2half(ce.q));  // (c1,c2)
        const h2 lv  = __halves2half2(__high2half(lf),   __low2half(ce.p));  // (cl,c0)
        const h2 rv  = __halves2half2(__high2half(ce.q), __low2half(rt));    // (c3,cr)
        HQ o;
        o.p = __hmin2(__hmin2(__hmin2(up.p, dn.p), ce.p), __hmin2(lv,  mid));
        o.q = __hmin2(__hmin2(__hmin2(up.q, dn.q), ce.q), __hmin2(mid, rv));
        if (TOPB) { if (r < 0)      o = mkHQ(INF2, INF2); }
        if (BOTB) { if (r >= IMG_H) o = mkHQ(INF2, INF2); }
        L[j][u] = o;
        if (WRITE_E && j == T) {
            if (r >= b0 && r < b1 && outok) stHQ(eoP - T * ROWQ, o);   // row Y-T
        }
    }

    // Deltas: delta_k at row y = Y - k - 2
#pragma unroll
    for (int k = 0; k < T; ++k) {
        const int y = Y - k - 2;
        if (y < b0 || y >= b1) continue;

        HQ A = L[k + 1][hh2];
        const HQ B = L[k + 1][h1];
        HQ C = L[k + 1][u];
        if (TOPB) { if (y == 0)         A = mkHQ(NINF2, NINF2); }
        if (BOTB) { if (y == IMG_H - 1) C = mkHQ(NINF2, NINF2); }

        const h2 vmP = __hmax2(__hmax2(A.p, B.p), C.p);
        const h2 vmQ = __hmax2(__hmax2(A.q, B.q), C.q);
        const h2 lf = shup(vmQ);
        const h2 rt = shdn(vmP);
        const h2 mid = __halves2half2(__high2half(vmP), __low2half(vmQ));
        const h2 lv  = __halves2half2(ledge ? NINFh : __high2half(lf), __low2half(vmP));
        const h2 rv  = __halves2half2(__high2half(vmQ), redge ? NINFh : __low2half(rt));
        const h2 opP = __hmax2(vmP, __hmax2(lv,  mid));
        const h2 opQ = __hmax2(vmQ, __hmax2(mid, rv));

        // delta = relu(e - op): e,op in [0,1] -> SAT subtract is exact relu (fma pipe)
        const HQ e = L[k][hh2];
        const h2 dP = __hsub2_sat(e.p, opP);
        const h2 dQ = __hsub2_sat(e.q, opQ);

        uint2* srow = ring + ((y & 7) << 5) + lane;
        HQ s;
        if (k == 0) {
            if (INIT) s = mkHQ(ZERO2, ZERO2);
            else      s = scur;
        } else {
            s = ldHQ(srow);
        }
        // s += relu(d - s*d): SAT fma clamps negatives to 0 = exact relu (fma pipe)
        s.p = __hadd2(s.p, __hfma2_sat(__hneg2(s.p), dP, dP));
        s.q = __hadd2(s.q, __hfma2_sat(__hneg2(s.q), dQ, dQ));

        if (k == T - 1) {
            if (outok) {
                if (FUSE) {
                    const float2 f0 = __half22float2(s.p);
                    const float2 f1 = __half22float2(s.q);
                    acc_p += f0.x * ocur.x + f0.y * ocur.y + f1.x * ocur.z + f1.y * ocur.w;
                    acc_s += f0.x + f0.y + f1.x + f1.y;
                } else {
                    stHQ(skP - (T + 1) * ROWQ, s);        // row Y-T-1
                }
            }
        } else {
            stHQ(srow, s);
        }
    }
}

template <int T, bool INIT, bool WRITE_E, bool TOPB, bool BOTB, bool FUSE>
__device__ __forceinline__ void sweep(
    const float4* in4f, const uint2* in2h, uint2* eout2,
    uint2* skel2, const float4* other4,
    uint2* __restrict__ ring, double* __restrict__ sums, int t_idx,
    int lane, int gq, bool loadok, bool outok, bool ledge, bool redge,
    int b0, int b1)
{
    // NSTEPS >= (b1-b0) + 2T + 4, multiple of 3 (max band = 94 rows)
    constexpr int NST = (T == 6) ? 111 : 108;
    const h2 INF2  = hc(0x7C00);
    const h2 ZERO2 = hc(0x0000);

    HQ L[T + 1][3];
#pragma unroll
    for (int j = 0; j <= T; ++j)
#pragma unroll
        for (int s = 0; s < 3; ++s)
            L[j][s] = mkHQ(INF2, INF2);

    const int Ys = b0 - (T + 3);

    // Stream pointers at "row Ys-1"; first do_step advances them to row Ys.
    const float4* inPf = INIT    ? (in4f   + (Ys - 1) * ROWQ + gq) : nullptr;
    const uint2*  inPh = !INIT   ? (in2h   + (Ys - 1) * ROWQ + gq) : nullptr;
    uint2*        skP  = skel2   + (Ys - 1) * ROWQ + gq;
    const float4* otP  = FUSE    ? (other4 + (Ys - 1) * ROWQ + gq) : nullptr;
    uint2*        eoP  = WRITE_E ? (eout2  + (Ys - 1) * ROWQ + gq) : nullptr;

    // Prime the double-buffered input stream: nx0 = row Ys, nx1 = row Ys+1.
    HQ nx0 = mkHQ(INF2, INF2), nx1 = mkHQ(INF2, INF2);
    {
        bool ok0 = loadok, ok1 = loadok;
        if (TOPB) { ok0 = ok0 && (Ys >= 0); ok1 = ok1 && (Ys + 1 >= 0); }
        if (ok0) {
            if (INIT) {
                float4 f = in4f[Ys * ROWQ + gq];
                nx0.p = __floats2half2_rn(f.x, f.y);
                nx0.q = __floats2half2_rn(f.z, f.w);
            } else {
                nx0 = ldHQ(in2h + Ys * ROWQ + gq);
            }
        }
        if (ok1) {
            if (INIT) {
                float4 f = in4f[(Ys + 1) * ROWQ + gq];
                nx1.p = __floats2half2_rn(f.x, f.y);
                nx1.q = __floats2half2_rn(f.z, f.w);
            } else {
                nx1 = ldHQ(in2h + (Ys + 1) * ROWQ + gq);
            }
        }
    }
    HQ sn0 = mkHQ(ZERO2, ZERO2), sn1 = mkHQ(ZERO2, ZERO2);
    float4 onxt = make_float4(0.0f, 0.0f, 0.0f, 0.0f);
    float acc_p = 0.0f, acc_s = 0.0f;

    for (int d = 0; d < NST; d += 3) {
        do_step<T, 0, INIT, WRITE_E, TOPB, BOTB, FUSE>(Ys + d,     L, nx0, nx1, sn0, sn1, onxt,
            inPf, inPh, skP, otP, eoP, ring, acc_p, acc_s,
            lane, loadok, outok, ledge, redge, b0, b1);
        do_step<T, 1, INIT, WRITE_E, TOPB, BOTB, FUSE>(Ys + d + 1, L, nx0, nx1, sn0, sn1, onxt,
            inPf, inPh, skP, otP, eoP, ring, acc_p, acc_s,
            lane, loadok, outok, ledge, redge, b0, b1);
        do_step<T, 2, INIT, WRITE_E, TOPB, BOTB, FUSE>(Ys + d + 2, L, nx0, nx1, sn0, sn1, onxt,
            inPf, inPh, skP, otP, eoP, ring, acc_p, acc_s,
            lane, loadok, outok, ledge, redge, b0, b1);
    }

    if (FUSE) {
#pragma unroll
        for (int off = 16; off > 0; off >>= 1) {
            acc_p += __shfl_down_sync(FULLM, acc_p, off);
            acc_s += __shfl_down_sync(FULLM, acc_s, off);
        }
        if (lane == 0) {
            atomicAdd(&sums[2 * t_idx],     (double)acc_p);
            atomicAdd(&sums[2 * t_idx + 1], (double)acc_s);
        }
    }
}

// Warp-autonomous erosion tower: no block barriers. fp16 tower data.
template <int T, bool INIT, bool WRITE_E, bool FUSE>
__global__ __launch_bounds__(128, 6)
void tower(const float* __restrict__ p0, const float* __restrict__ p1,
           const float* __restrict__ o0, const float* __restrict__ o1,
           const __half* __restrict__ hin, __half* __restrict__ eout,
           __half* __restrict__ gskel)
{
    __shared__ uint2 ring[4][8 * 32];

    const int wid  = threadIdx.x >> 5;
    const int lane = threadIdx.x & 31;
    const int w    = blockIdx.x * 4 + wid;
    const int n    = w / (NBANDS * STRIPS);
    const int rem  = w % (NBANDS * STRIPS);
    const int band = rem / STRIPS;
    const int strip = rem % STRIPS;
    const int b0 = band * BROW0;
    const int b1 = (band == NBANDS - 1) ? IMG_H : (b0 + BROW0);

    const int gq = 26 * strip - 3 + lane;
    const bool loadok = (gq >= 0) && (gq < ROWQ);
    const bool outok  = (lane >= 3) && (lane < 29) && (gq < ROWQ);
    const bool ledge  = (gq == 0);
    const bool redge  = (gq == ROWQ - 1);

    const float* srcf = nullptr;
    if (INIT) srcf = (n < N_IMG) ? (p0 + (size_t)n * IMG_PIX)
                                 : (p1 + (size_t)(n - N_IMG) * IMG_PIX);
    const __half* srch = INIT ? nullptr : (hin + (size_t)n * IMG_PIX);
    const float* oth = nullptr;
    const int t_idx = (n >= N_IMG) ? 1 : 0;
    if (FUSE) oth = (n < N_IMG) ? (o0 + (size_t)n * IMG_PIX)
                                : (o1 + (size_t)(n - N_IMG) * IMG_PIX);

    const float4* in4f  = (const float4*)srcf;
    const uint2*  in2h  = (const uint2*)srch;
    uint2*        eout2 = (uint2*)(WRITE_E ? (eout + (size_t)n * IMG_PIX) : nullptr);
    uint2*        skel2 = (uint2*)(gskel + (size_t)n * IMG_PIX);
    const float4* oth4  = (const float4*)oth;
    uint2* myring = &ring[wid][0];

    if (band == 0)
        sweep<T, INIT, WRITE_E, true,  false, FUSE>(in4f, in2h, eout2, skel2, oth4, myring,
            g_sums, t_idx, lane, gq, loadok, outok, ledge, redge, b0, b1);
    else if (band == NBANDS - 1)
        sweep<T, INIT, WRITE_E, false, true,  FUSE>(in4f, in2h, eout2, skel2, oth4, myring,
            g_sums, t_idx, lane, gq, loadok, outok, ledge, redge, b0, b1);
    else
        sweep<T, INIT, WRITE_E, false, false, FUSE>(in4f, in2h, eout2, skel2, oth4, myring,
            g_sums, t_idx, lane, gq, loadok, outok, ledge, redge, b0, b1);
}

__global__ void zero_sums(double* sums) {
    if (threadIdx.x < 4) sums[threadIdx.x] = 0.0;
}

__global__ void finalize_cldice(const double* __restrict__ sums, float* __restrict__ out) {
    const double tprec = (sums[0] + SMOOTH) / (sums[1] + SMOOTH);
    const double tsens = (sums[2] + SMOOTH) / (sums[3] + SMOOTH);
    out[0] = (float)(1.0 - 2.0 * (tprec * tsens) / (tprec + tsens));
}

extern "C" void kernel_launch(void* const* d_in, const int* in_sizes, int n_in,
                              void* d_out, int out_size) {
    const float* target = (const float*)d_in[0];
    const float* inputs = (const float*)d_in[1];
    float* out = (float*)d_out;

    static __half* bufA = nullptr;
    static __half* bufB = nullptr;
    static __half* skel = nullptr;
    static double* sums = nullptr;
    if (!bufA) {
        cudaGetSymbolAddress((void**)&bufA, g_bufA);
        cudaGetSymbolAddress((void**)&bufB, g_bufB);
        cudaGetSymbolAddress((void**)&skel, g_skel);
        cudaGetSymbolAddress((void**)&sums, g_sums);
    }

    // warps: 64 images x 11 bands x 10 strips = 7040 -> 1760 blocks x 4 warps
    // (6 blocks/SM -> 888 slots -> 1.98 waves, 99% packed)
    const int NBLK = (2 * N_IMG * NBANDS * STRIPS) / 4;
    const dim3 block(128);

    zero_sums<<<1, 32>>>(sums);

    // Erosion tower E_0..E_26, deltas 0..25: passes T = 6,5,5,5,5 (fp16).
    // Pass 1 converts fp32->fp16; last pass fuses the skel/other reduction.
    tower<6, true,  true,  false><<<NBLK, block>>>(inputs, target, nullptr, nullptr,
                                                   nullptr, bufA, skel);
    tower<5, false, true,  false><<<NBLK, block>>>(nullptr, nullptr, nullptr, nullptr,
                                                   bufA, bufB, skel);
    tower<5, false, true,  false><<<NBLK, block>>>(nullptr, nullptr, nullptr, nullptr,
                                                   bufB, bufA, skel);
    tower<5, false, true,  false><<<NBLK, block>>>(nullptr, nullptr, nullptr, nullptr,
                                                   bufA, bufB, skel);
    tower<5, false, false, true ><<<NBLK, block>>>(nullptr, nullptr, target, inputs,
                                                   bufB, nullptr, skel);

    finalize_cldice<<<1, 1>>>(sums, out);
}

// round 17
// speedup vs baseline: 1.0596x; 1.0596x over previous
#include <cuda_runtime.h>
#include <cuda_fp16.h>
#include <cstdint>

#define IMG_W   1024
#define IMG_H   1024
#define IMG_PIX (IMG_W * IMG_H)
#define N_IMG   32
#define TOTAL_F ((size_t)N_IMG * IMG_PIX)
#define SMOOTH  1e-5
#define FULLM   0xffffffffu
#define NBANDS  11                    // bands 0..9: 93 rows; band 10: 94 rows
#define BROW0   93
#define STRIPS  10
#define ROWQ    (IMG_W / 4)           // quads (4 cols) per row

typedef __half2 h2;
struct HQ { h2 p, q; };               // 4 columns: p=(c0,c1), q=(c2,c3)

// Scratch (no cudaMalloc allowed): fp16 intermediates
__device__ __half g_bufA[2 * N_IMG * IMG_PIX];
__device__ __half g_bufB[2 * N_IMG * IMG_PIX];
__device__ __half g_skel[2 * N_IMG * IMG_PIX];
__device__ double g_sums[4];

__device__ __forceinline__ HQ mkHQ(h2 a, h2 b) { HQ r; r.p = a; r.q = b; return r; }
__device__ __forceinline__ h2 hc(unsigned short u) { return __half2half2(__ushort_as_half(u)); }
__device__ __forceinline__ HQ ldHQ(const uint2* p) {
    uint2 u = *p; HQ v;
    v.p = *(h2*)&u.x; v.q = *(h2*)&u.y; return v;
}
__device__ __forceinline__ void stHQ(uint2* p, HQ v) {
    uint2 u; u.x = *(unsigned*)&v.p; u.y = *(unsigned*)&v.q; *p = u;
}
__device__ __forceinline__ h2 shup(h2 v) {
    unsigned u = *(unsigned*)&v; u = __shfl_up_sync(FULLM, u, 1); return *(h2*)&u;
}
__device__ __forceinline__ h2 shdn(h2 v) {
    unsigned u = *(unsigned*)&v; u = __shfl_down_sync(FULLM, u, 1); return *(h2*)&u;
}

// One sweep step at row Y, ring slot U (compile-time). fp16 tower.
// Ring invariant after step Y: L[j][U] = level-j row (Y-j); (U+2)%3 = that row-1; (U+1)%3 = row-2.
// Skel partials live in the register chain sk[0..T-2]: after step Y, sk[k] holds the
// partial skel of row Y-2-k (updated through delta_k). Deltas iterate k DESCENDING so
// each k reads sk[k-1] (previous step's value for the same row) before it is rewritten.
template <int T, int U, bool INIT, bool WRITE_E, bool TOPB, bool BOTB, bool FUSE>
__device__ __forceinline__ void do_step(
    int Y, HQ (&L)[T + 1][3], HQ (&sk)[T - 1], HQ& nxt, HQ& snxt, float4& onxt,
    const float4*& inPf, const uint2*& inPh, uint2*& skP, const float4*& otP, uint2*& eoP,
    float& acc_p, float& acc_s,
    int lane, bool loadok, bool outok, bool ledge, bool redge,
    int b0, int b1)
{
    const h2 INF2  = hc(0x7C00);
    const h2 NINF2 = hc(0xFC00);
    const h2 ZERO2 = hc(0x0000);
    const __half NINFh = __ushort_as_half(0xFC00);
    constexpr int u  = U;
    constexpr int h1 = (U + 2) % 3;
    constexpr int hh2 = (U + 1) % 3;

    // Advance stream pointers to row Y.
    if (INIT) inPf += ROWQ; else inPh += ROWQ;
    skP += ROWQ;
    if (FUSE) otP += ROWQ;
    if (WRITE_E) eoP += ROWQ;

    // Consume prefetched input row Y; prefetch row Y+1.
    L[0][u] = nxt;
    {
        const int yy = Y + 1;
        bool ok = loadok;
        if (TOPB) ok = ok && (yy >= 0);
        if (BOTB) ok = ok && (yy < IMG_H);
        HQ v = mkHQ(INF2, INF2);
        if (ok) {
            if (INIT) {
                float4 f = inPf[ROWQ];
                v.p = __floats2half2_rn(f.x, f.y);
                v.q = __floats2half2_rn(f.z, f.w);
            } else {
                v = ldHQ(inPh + ROWQ);
            }
        }
        nxt = v;
    }
    // Consume prefetched skel row (Y-2); prefetch row Y-1.
    HQ scur = snxt;
    if (!INIT) {
        const int yy = Y - 1;
        HQ sv = mkHQ(ZERO2, ZERO2);
        if (yy >= b0 && yy < b1 && outok) sv = ldHQ(skP - ROWQ);
        snxt = sv;
    }
    // Consume prefetched other row (Y-T-1, fp32); prefetch row Y-T.
    float4 ocur = onxt;
    if (FUSE) {
        const int yy = Y - T;
        float4 ov = make_float4(0.0f, 0.0f, 0.0f, 0.0f);
        if (yy >= b0 && yy < b1 && outok) ov = otP[-T * ROWQ];
        onxt = ov;
    }

    // Erosion levels: level j computes row r = Y - j from level j-1 rows r-1..r+1
#pragma unroll
    for (int j = 1; j <= T; ++j) {
        const int r = Y - j;
        const HQ up = L[j - 1][hh2];
        const HQ ce = L[j - 1][h1];
        const HQ dn = L[j - 1][u];
        const h2 lf = shup(ce.q);   // left neighbor's (c2,c3)
        const h2 rt = shdn(ce.p);   // right neighbor's (c0,c1)
        const h2 mid = __halves2half2(__high2half(ce.p), __low2half(ce.q));  // (c1,c2)
        const h2 lv  = __halves2half2(__high2half(lf),   __low2half(ce.p));  // (cl,c0)
        const h2 rv  = __halves2half2(__high2half(ce.q), __low2half(rt));    // (c3,cr)
        HQ o;
        o.p = __hmin2(__hmin2(__hmin2(up.p, dn.p), ce.p), __hmin2(lv,  mid));
        o.q = __hmin2(__hmin2(__hmin2(up.q, dn.q), ce.q), __hmin2(mid, rv));
        if (TOPB) { if (r < 0)      o = mkHQ(INF2, INF2); }
        if (BOTB) { if (r >= IMG_H) o = mkHQ(INF2, INF2); }
        L[j][u] = o;
        if (WRITE_E && j == T) {
            if (r >= b0 && r < b1 && outok) stHQ(eoP - T * ROWQ, o);   // row Y-T
        }
    }

    // Deltas: delta_k at row y = Y - k - 2 (descending k: read sk[k-1] before rewrite)
#pragma unroll
    for (int k = T - 1; k >= 0; --k) {
        const int y = Y - k - 2;
        if (y < b0 || y >= b1) continue;

        HQ A = L[k + 1][hh2];
        const HQ B = L[k + 1][h1];
        HQ C = L[k + 1][u];
        if (TOPB) { if (y == 0)         A = mkHQ(NINF2, NINF2); }
        if (BOTB) { if (y == IMG_H - 1) C = mkHQ(NINF2, NINF2); }

        const h2 vmP = __hmax2(__hmax2(A.p, B.p), C.p);
        const h2 vmQ = __hmax2(__hmax2(A.q, B.q), C.q);
        const h2 lf = shup(vmQ);
        const h2 rt = shdn(vmP);
        const h2 mid = __halves2half2(__high2half(vmP), __low2half(vmQ));
        const h2 lv  = __halves2half2(ledge ? NINFh : __high2half(lf), __low2half(vmP));
        const h2 rv  = __halves2half2(__high2half(vmQ), redge ? NINFh : __low2half(rt));
        const h2 opP = __hmax2(vmP, __hmax2(lv,  mid));
        const h2 opQ = __hmax2(vmQ, __hmax2(mid, rv));

        // delta = relu(e - op): e,op in [0,1] -> SAT subtract is exact relu (fma pipe)
        const HQ e = L[k][hh2];
        const h2 dP = __hsub2_sat(e.p, opP);
        const h2 dQ = __hsub2_sat(e.q, opQ);

        HQ s;
        if (k == 0) {
            if (INIT) s = mkHQ(ZERO2, ZERO2);
            else      s = scur;
        } else {
            s = sk[k - 1];
        }
        // s += relu(d - s*d): SAT fma clamps negatives to 0 = exact relu (fma pipe)
        s.p = __hadd2(s.p, __hfma2_sat(__hneg2(s.p), dP, dP));
        s.q = __hadd2(s.q, __hfma2_sat(__hneg2(s.q), dQ, dQ));

        if (k == T - 1) {
            if (outok) {
                if (FUSE) {
                    const float2 f0 = __half22float2(s.p);
                    const float2 f1 = __half22float2(s.q);
                    acc_p += f0.x * ocur.x + f0.y * ocur.y + f1.x * ocur.z + f1.y * ocur.w;
                    acc_s += f0.x + f0.y + f1.x + f1.y;
                } else {
                    stHQ(skP - (T + 1) * ROWQ, s);        // row Y-T-1
                }
            }
        } else {
            sk[k] = s;
        }
    }
}

template <int T, bool INIT, bool WRITE_E, bool TOPB, bool BOTB, bool FUSE>
__device__ __forceinline__ void sweep(
    const float4* in4f, const uint2* in2h, uint2* eout2,
    uint2* skel2, const float4* other4,
    double* __restrict__ sums, int t_idx,
    int lane, int gq, bool loadok, bool outok, bool ledge, bool redge,
    int b0, int b1)
{
    // NSTEPS >= (b1-b0) + 2T + 4, multiple of 3 (max band = 94 rows)
    constexpr int NST = (T == 6) ? 111 : 108;
    const h2 INF2  = hc(0x7C00);
    const h2 ZERO2 = hc(0x0000);

    HQ L[T + 1][3];
#pragma unroll
    for (int j = 0; j <= T; ++j)
#pragma unroll
        for (int s = 0; s < 3; ++s)
            L[j][s] = mkHQ(INF2, INF2);

    HQ sk[T - 1];
#pragma unroll
    for (int k = 0; k < T - 1; ++k) sk[k] = mkHQ(ZERO2, ZERO2);

    const int Ys = b0 - (T + 3);

    // Stream pointers at "row Ys-1"; first do_step advances them to row Ys.
    const float4* inPf = INIT    ? (in4f   + (Ys - 1) * ROWQ + gq) : nullptr;
    const uint2*  inPh = !INIT   ? (in2h   + (Ys - 1) * ROWQ + gq) : nullptr;
    uint2*        skP  = skel2   + (Ys - 1) * ROWQ + gq;
    const float4* otP  = FUSE    ? (other4 + (Ys - 1) * ROWQ + gq) : nullptr;
    uint2*        eoP  = WRITE_E ? (eout2  + (Ys - 1) * ROWQ + gq) : nullptr;

    HQ nxt = mkHQ(INF2, INF2);
    {
        bool ok = loadok;
        if (TOPB) ok = ok && (Ys >= 0);
        if (ok) {
            if (INIT) {
                float4 f = in4f[Ys * ROWQ + gq];
                nxt.p = __floats2half2_rn(f.x, f.y);
                nxt.q = __floats2half2_rn(f.z, f.w);
            } else {
                nxt = ldHQ(in2h + Ys * ROWQ + gq);
            }
        }
    }
    HQ snxt = mkHQ(ZERO2, ZERO2);
    float4 onxt = make_float4(0.0f, 0.0f, 0.0f, 0.0f);
    float acc_p = 0.0f, acc_s = 0.0f;

    for (int d = 0; d < NST; d += 3) {
        do_step<T, 0, INIT, WRITE_E, TOPB, BOTB, FUSE>(Ys + d,     L, sk, nxt, snxt, onxt,
            inPf, inPh, skP, otP, eoP, acc_p, acc_s,
            lane, loadok, outok, ledge, redge, b0, b1);
        do_step<T, 1, INIT, WRITE_E, TOPB, BOTB, FUSE>(Ys + d + 1, L, sk, nxt, snxt, onxt,
            inPf, inPh, skP, otP, eoP, acc_p, acc_s,
            lane, loadok, outok, ledge, redge, b0, b1);
        do_step<T, 2, INIT, WRITE_E, TOPB, BOTB, FUSE>(Ys + d + 2, L, sk, nxt, snxt, onxt,
            inPf, inPh, skP, otP, eoP, acc_p, acc_s,
            lane, loadok, outok, ledge, redge, b0, b1);
    }

    if (FUSE) {
#pragma unroll
        for (int off = 16; off > 0; off >>= 1) {
            acc_p += __shfl_down_sync(FULLM, acc_p, off);
            acc_s += __shfl_down_sync(FULLM, acc_s, off);
        }
        if (lane == 0) {
            atomicAdd(&sums[2 * t_idx],     (double)acc_p);
            atomicAdd(&sums[2 * t_idx + 1], (double)acc_s);
        }
    }
}

// Warp-autonomous erosion tower: no block barriers, no shared memory. fp16 tower data.
template <int T, bool INIT, bool WRITE_E, bool FUSE>
__global__ __launch_bounds__(128, 6)
void tower(const float* __restrict__ p0, const float* __restrict__ p1,
           const float* __restrict__ o0, const float* __restrict__ o1,
           const __half* __restrict__ hin, __half* __restrict__ eout,
           __half* __restrict__ gskel)
{
    const int wid  = threadIdx.x >> 5;
    const int lane = threadIdx.x & 31;
    const int w    = blockIdx.x * 4 + wid;
    const int n    = w / (NBANDS * STRIPS);
    const int rem  = w % (NBANDS * STRIPS);
    const int band = rem / STRIPS;
    const int strip = rem % STRIPS;
    const int b0 = band * BROW0;
    const int b1 = (band == NBANDS - 1) ? IMG_H : (b0 + BROW0);

    const int gq = 26 * strip - 3 + lane;
    const bool loadok = (gq >= 0) && (gq < ROWQ);
    const bool outok  = (lane >= 3) && (lane < 29) && (gq < ROWQ);
    const bool ledge  = (gq == 0);
    const bool redge  = (gq == ROWQ - 1);

    const float* srcf = nullptr;
    if (INIT) srcf = (n < N_IMG) ? (p0 + (size_t)n * IMG_PIX)
                                 : (p1 + (size_t)(n - N_IMG) * IMG_PIX);
    const __half* srch = INIT ? nullptr : (hin + (size_t)n * IMG_PIX);
    const float* oth = nullptr;
    const int t_idx = (n >= N_IMG) ? 1 : 0;
    if (FUSE) oth = (n < N_IMG) ? (o0 + (size_t)n * IMG_PIX)
                                : (o1 + (size_t)(n - N_IMG) * IMG_PIX);

    const float4* in4f  = (const float4*)srcf;
    const uint2*  in2h  = (const uint2*)srch;
    uint2*        eout2 = (uint2*)(WRITE_E ? (eout + (size_t)n * IMG_PIX) : nullptr);
    uint2*        skel2 = (uint2*)(gskel + (size_t)n * IMG_PIX);
    const float4* oth4  = (const float4*)oth;

    if (band == 0)
        sweep<T, INIT, WRITE_E, true,  false, FUSE>(in4f, in2h, eout2, skel2, oth4,
            g_sums, t_idx, lane, gq, loadok, outok, ledge, redge, b0, b1);
    else if (band == NBANDS - 1)
        sweep<T, INIT, WRITE_E, false, true,  FUSE>(in4f, in2h, eout2, skel2, oth4,
            g_sums, t_idx, lane, gq, loadok, outok, ledge, redge, b0, b1);
    else
        sweep<T, INIT, WRITE_E, false, false, FUSE>(in4f, in2h, eout2, skel2, oth4,
            g_sums, t_idx, lane, gq, loadok, outok, ledge, redge, b0, b1);
}

__global__ void zero_sums(double* sums) {
    if (threadIdx.x < 4) sums[threadIdx.x] = 0.0;
}

__global__ void finalize_cldice(const double* __restrict__ sums, float* __restrict__ out) {
    const double tprec = (sums[0] + SMOOTH) / (sums[1] + SMOOTH);
    const double tsens = (sums[2] + SMOOTH) / (sums[3] + SMOOTH);
    out[0] = (float)(1.0 - 2.0 * (tprec * tsens) / (tprec + tsens));
}

extern "C" void kernel_launch(void* const* d_in, const int* in_sizes, int n_in,
                              void* d_out, int out_size) {
    const float* target = (const float*)d_in[0];
    const float* inputs = (const float*)d_in[1];
    float* out = (float*)d_out;

    static __half* bufA = nullptr;
    static __half* bufB = nullptr;
    static __half* skel = nullptr;
    static double* sums = nullptr;
    if (!bufA) {
        cudaGetSymbolAddress((void**)&bufA, g_bufA);
        cudaGetSymbolAddress((void**)&bufB, g_bufB);
        cudaGetSymbolAddress((void**)&skel, g_skel);
        cudaGetSymbolAddress((void**)&sums, g_sums);
    }

    // warps: 64 images x 11 bands x 10 strips = 7040 -> 1760 blocks x 4 warps
    // (6 blocks/SM -> 888 slots -> 1.98 waves, 99% packed)
    const int NBLK = (2 * N_IMG * NBANDS * STRIPS) / 4;
    const dim3 block(128);

    zero_sums<<<1, 32>>>(sums);

    // Erosion tower E_0..E_26, deltas 0..25: passes T = 6,5,5,5,5 (fp16).
    // Pass 1 converts fp32->fp16; last pass fuses the skel/other reduction.
    tower<6, true,  true,  false><<<NBLK, block>>>(inputs, target, nullptr, nullptr,
                                                   nullptr, bufA, skel);
    tower<5, false, true,  false><<<NBLK, block>>>(nullptr, nullptr, nullptr, nullptr,
                                                   bufA, bufB, skel);
    tower<5, false, true,  false><<<NBLK, block>>>(nullptr, nullptr, nullptr, nullptr,
                                                   bufB, bufA, skel);
    tower<5, false, true,  false><<<NBLK, block>>>(nullptr, nullptr, nullptr, nullptr,
                                                   bufA, bufB, skel);
    tower<5, false, false, true ><<<NBLK, block>>>(nullptr, nullptr, target, inputs,
                                                   bufB, nullptr, skel);

    finalize_cldice<<<1, 1>>>(sums, out);
}